// round 4
// baseline (speedup 1.0000x reference)
#include <cuda_runtime.h>
#include <cuda_bf16.h>
#include <cstdint>

// ---------------- problem dims ----------------
#define TT 2048
#define KD 2048
#define ID 1024
#define NE 8
#define GSZ 64
#define BM 128
#define MAXT 56
#define ROWS_CAP 7168

#define GU_SMEM 102400
#define DN_SMEM 86016

__device__ __constant__ float c_lut[16] = {
    0.0f, 0.5f, 1.0f, 1.5f, 2.0f, 3.0f, 4.0f, 6.0f,
   -0.0f,-0.5f,-1.0f,-1.5f,-2.0f,-3.0f,-4.0f,-6.0f };

// ---------------- scratch ----------------
__device__ int   g_tok[ROWS_CAP];
__device__ float g_w[ROWS_CAP];
__device__ int   g_tile_e[MAXT];
__device__ int   g_tile_b[MAXT];
__device__ int   g_ntiles;
__device__ int   g_rowof[TT * 3];
__device__ __nv_bfloat16 g_xh[(size_t)TT * KD];
__device__ __nv_bfloat16 g_xl[(size_t)TT * KD];
__device__ __nv_bfloat16 g_ah[(size_t)ROWS_CAP * ID];
__device__ __nv_bfloat16 g_al[(size_t)ROWS_CAP * ID];
__device__ float g_y[(size_t)ROWS_CAP * KD];

// ---------------- helpers ----------------
static __device__ __forceinline__ uint32_t swz128(uint32_t o) { return o ^ ((o >> 3) & 0x70); }
static __device__ __forceinline__ uint32_t smem_u32(const void* p) {
    uint32_t a;
    asm("{ .reg .u64 t; cvta.to.shared.u64 t, %1; cvt.u32.u64 %0, t; }" : "=r"(a) : "l"(p));
    return a;
}
static __device__ __forceinline__ void ldmx4(uint32_t* r, uint32_t addr) {
    asm volatile("ldmatrix.sync.aligned.m8n8.x4.shared.b16 {%0,%1,%2,%3}, [%4];"
        : "=r"(r[0]), "=r"(r[1]), "=r"(r[2]), "=r"(r[3]) : "r"(addr));
}
static __device__ __forceinline__ void mma16816(float* d, const uint32_t* a,
                                                uint32_t b0, uint32_t b1, const float* c) {
    asm volatile(
        "mma.sync.aligned.m16n8k16.row.col.f32.bf16.bf16.f32 "
        "{%0,%1,%2,%3},{%4,%5,%6,%7},{%8,%9},{%10,%11,%12,%13};"
        : "=f"(d[0]), "=f"(d[1]), "=f"(d[2]), "=f"(d[3])
        : "r"(a[0]), "r"(a[1]), "r"(a[2]), "r"(a[3]), "r"(b0), "r"(b1),
          "f"(c[0]), "f"(c[1]), "f"(c[2]), "f"(c[3]));
}
static __device__ __forceinline__ void cpasync16(uint32_t dst, const void* src, int srcsize) {
    asm volatile("cp.async.cg.shared.global [%0], [%1], 16, %2;"
                 :: "r"(dst), "l"(src), "r"(srcsize));
}
#define CP_COMMIT asm volatile("cp.async.commit_group;" ::: "memory")
#define CP_WAIT0  asm volatile("cp.async.wait_group 0;" ::: "memory")
#define CP_WAIT1  asm volatile("cp.async.wait_group 1;" ::: "memory")

static __device__ __forceinline__ uint32_t pk2(float a, float b) {
    __nv_bfloat162 t = __floats2bfloat162_rn(a, b);
    return *reinterpret_cast<uint32_t*>(&t);
}
static __device__ __forceinline__ float silu_f(float g) { return g / (1.0f + __expf(-g)); }

// ---------------------------------------------------------------------------
// routing
// ---------------------------------------------------------------------------
__global__ void k_route(const int* __restrict__ eids, const float* __restrict__ probs)
{
    __shared__ int cnt[NE];
    __shared__ int offs[NE];
    __shared__ int baseE;
    int tid = threadIdx.x;
    if (tid < NE) cnt[tid] = 0;
    __syncthreads();
    for (int i = tid; i < TT * 2; i += blockDim.x) atomicAdd(&cnt[eids[i]], 1);
    __syncthreads();
    if (tid == 0) {
        int b = 0, tile = 0;
        for (int e = 0; e < NE; e++) {
            offs[e] = b;
            int nt = (cnt[e] + BM - 1) / BM;
            for (int j = 0; j < nt; j++) { g_tile_e[tile] = e; g_tile_b[tile] = b + j * BM; tile++; }
            b += nt * BM;
        }
        baseE = b;
        for (int j = 0; j < TT / BM; j++) { g_tile_e[tile] = NE; g_tile_b[tile] = b + j * BM; tile++; }
        g_ntiles = tile;
    }
    __syncthreads();
    for (int i = tid; i < ROWS_CAP; i += blockDim.x) { g_tok[i] = -1; g_w[i] = 0.0f; }
    __syncthreads();
    for (int i = tid; i < TT * 2; i += blockDim.x) {
        int e = eids[i];
        int pos = atomicAdd(&offs[e], 1);
        int t = i >> 1;
        g_tok[pos] = t;
        g_w[pos] = probs[i];
        g_rowof[t * 3 + (i & 1)] = pos;
    }
    int bs = baseE;
    for (int t = tid; t < TT; t += blockDim.x) {
        g_tok[bs + t] = t;
        g_w[bs + t] = 1.0f;
        g_rowof[t * 3 + 2] = bs + t;
    }
}

// ---------------------------------------------------------------------------
// split x into bf16 hi/lo
// ---------------------------------------------------------------------------
__global__ __launch_bounds__(256) void k_splitx(const float* __restrict__ x)
{
    int idx = blockIdx.x * blockDim.x + threadIdx.x;
    float4 v = ((const float4*)x)[idx];
    float a[4] = {v.x, v.y, v.z, v.w};
    float hf[4], lf[4];
    #pragma unroll
    for (int i = 0; i < 4; i++) {
        hf[i] = __bfloat162float(__float2bfloat16_rn(a[i]));
        lf[i] = a[i] - hf[i];
    }
    ((uint2*)g_xh)[idx] = make_uint2(pk2(hf[0], hf[1]), pk2(hf[2], hf[3]));
    ((uint2*)g_xl)[idx] = make_uint2(pk2(lf[0], lf[1]), pk2(lf[2], lf[3]));
}

// ---------------------------------------------------------------------------
// gate_up: block = 128 rows x (64 gate + 64 up cols). grid (MAXT, ID/64).
// Pipelined: STS B(kb+1) overlaps MMA(kb); cp.async depth-2 on A.
// ---------------------------------------------------------------------------
__global__ __launch_bounds__(256, 1)
void k_gu(const int* __restrict__ gup, const float* __restrict__ gus,
          const int* __restrict__ sgup, const float* __restrict__ sgus)
{
    extern __shared__ __align__(16) char sm[];
    int tile = blockIdx.x;
    if (tile >= g_ntiles) return;
    int e = g_tile_e[tile], rbase = g_tile_b[tile];
    int n0 = blockIdx.y * 64;
    const int* wp; const float* sp;
    if (e < NE) { wp = gup + (size_t)e * (KD / 8) * (2 * ID); sp = gus + (size_t)e * (KD / GSZ) * (2 * ID); }
    else        { wp = sgup; sp = sgus; }

    uint32_t* tbl = (uint32_t*)sm;
    float* ss = (float*)(sm + 1024);
    int* toks = (int*)(sm + 2048);
    uint32_t smb = smem_u32(sm);
    const int tid = threadIdx.x;

    {
        __nv_bfloat16 l0 = __float2bfloat16(c_lut[tid & 15]);
        __nv_bfloat16 l1 = __float2bfloat16(c_lut[(tid >> 4) & 15]);
        tbl[tid] = (uint32_t)*(uint16_t*)&l0 | ((uint32_t)*(uint16_t*)&l1 << 16);
    }
    if (tid < 128) toks[tid] = g_tok[rbase + tid];
    __syncthreads();

    int aoff[4]; uint32_t aswz[4];
    #pragma unroll
    for (int s = 0; s < 4; s++) {
        int idx = s * 256 + tid;
        int row = idx >> 3, q = idx & 7;
        int tok = toks[row];
        aoff[s] = (tok >= 0) ? (tok * (KD * 2) + q * 16) : -1;
        aswz[s] = swz128(row * 128 + q * 16);
    }
    int colw[4], jw4[4]; uint32_t dstB[4];
    #pragma unroll
    for (int i = 0; i < 4; i++) {
        int idx = i * 256 + tid;
        int n = idx >> 3, j = idx & 7;
        colw[i] = (n < 64) ? (n0 + n) : (ID + n0 + (n - 64));
        jw4[i] = j;
        dstB[i] = swz128(n * 128 + j * 16);
    }
    int scol = (tid < 64) ? (n0 + tid) : (ID + n0 + (tid - 64));

    int lane = tid & 31, wid = tid >> 5;
    int wm = (wid & 3) * 32, ngw = wid >> 2;
    int rowA0 = (wm + (lane & 15)) * 128;
    int khA = lane >> 4;
    int rowBt[4];
    #pragma unroll
    for (int t = 0; t < 4; t++) {
        int base = (t < 2) ? (ngw * 32 + t * 16) : (64 + ngw * 32 + (t - 2) * 16);
        rowBt[t] = (base + (lane & 7) + ((lane >> 4) << 3)) * 128;
    }
    int khB = (lane >> 3) & 1;

    float accF[2][8][4];
    #pragma unroll
    for (int a = 0; a < 2; a++)
        #pragma unroll
        for (int b = 0; b < 8; b++)
            #pragma unroll
            for (int c = 0; c < 4; c++) accF[a][b][c] = 0.f;
    float accC[2][8][4];
    const float zf4[4] = {0.f, 0.f, 0.f, 0.f};

    // ---- prologue: B(0) dequant+STS, prefetch B(1); A(0), A(1) cp.async ----
    uint32_t bw[4]; float sreg = 0.f;
    #pragma unroll
    for (int i = 0; i < 4; i++) bw[i] = (uint32_t)wp[(size_t)jw4[i] * (2 * ID) + colw[i]];
    if (tid < 128) sreg = sp[scol];
    {
        char* Bb = sm + 69632;                 // buf 0
        #pragma unroll
        for (int i = 0; i < 4; i++) {
            uint32_t w = bw[i];
            uint4 v;
            v.x = tbl[w & 255];         v.y = tbl[(w >> 8) & 255];
            v.z = tbl[(w >> 16) & 255]; v.w = tbl[w >> 24];
            *(uint4*)(Bb + dstB[i]) = v;
        }
        if (tid < 128) ss[tid] = sreg;
    }
    #pragma unroll
    for (int i = 0; i < 4; i++) bw[i] = (uint32_t)wp[(size_t)(8 + jw4[i]) * (2 * ID) + colw[i]];
    if (tid < 128) sreg = sp[(size_t)(2 * ID) + scol];

    #pragma unroll
    for (int s = 0; s < 4; s++) {
        int off = aoff[s];
        int sz = (off < 0) ? 0 : 16;
        int o = (off < 0) ? 0 : off;
        cpasync16(smb + 4096 + aswz[s],         (const char*)g_xh + o, sz);
        cpasync16(smb + 4096 + 16384 + aswz[s], (const char*)g_xl + o, sz);
    }
    CP_COMMIT;
    #pragma unroll
    for (int s = 0; s < 4; s++) {
        int off = aoff[s];
        int sz = (off < 0) ? 0 : 16;
        int o = (off < 0) ? 0 : off + 128;
        cpasync16(smb + 4096 + 32768 + aswz[s],         (const char*)g_xh + o, sz);
        cpasync16(smb + 4096 + 32768 + 16384 + aswz[s], (const char*)g_xl + o, sz);
    }
    CP_COMMIT;

    for (int kb = 0; kb < KD / 64; kb++) {
        int buf = kb & 1, nb = buf ^ 1;
        if (kb + 1 < KD / 64) { CP_WAIT1; } else { CP_WAIT0; }
        __syncthreads();
        // STS B(kb+1) into the other buffer (overlaps this chunk's MMAs)
        if (kb + 1 < KD / 64) {
            char* Bb = sm + 69632 + nb * 16384;
            #pragma unroll
            for (int i = 0; i < 4; i++) {
                uint32_t w = bw[i];
                uint4 v;
                v.x = tbl[w & 255];         v.y = tbl[(w >> 8) & 255];
                v.z = tbl[(w >> 16) & 255]; v.w = tbl[w >> 24];
                *(uint4*)(Bb + dstB[i]) = v;
            }
            if (tid < 128) ss[nb * 128 + tid] = sreg;
        }
        // MMA phase on current buffer
        uint32_t Ab = smb + 4096 + buf * 32768;
        uint32_t Bba = smb + 69632 + buf * 16384;
        #pragma unroll
        for (int ks = 0; ks < 4; ks++) {
            uint32_t bfr[4][4];
            #pragma unroll
            for (int t = 0; t < 4; t++)
                ldmx4(bfr[t], Bba + swz128(rowBt[t] + (ks * 2 + khB) * 16));
            #pragma unroll
            for (int pass = 0; pass < 2; pass++) {
                #pragma unroll
                for (int mf = 0; mf < 2; mf++) {
                    uint32_t a[4];
                    ldmx4(a, Ab + pass * 16384 + swz128(rowA0 + mf * 2048 + (ks * 2 + khA) * 16));
                    #pragma unroll
                    for (int nf = 0; nf < 8; nf++)
                        mma16816(accC[mf][nf], a,
                                 bfr[nf >> 1][(nf & 1) * 2], bfr[nf >> 1][(nf & 1) * 2 + 1],
                                 (ks == 0 && pass == 0) ? zf4 : accC[mf][nf]);
                }
            }
        }
        const float* ssb = ss + buf * 128;
        #pragma unroll
        for (int nf = 0; nf < 8; nf++) {
            int ci = ((nf < 4) ? 0 : 64) + ngw * 32 + (nf & 3) * 8 + (lane & 3) * 2;
            float s0 = ssb[ci], s1 = ssb[ci + 1];
            #pragma unroll
            for (int mf = 0; mf < 2; mf++) {
                accF[mf][nf][0] += s0 * accC[mf][nf][0];
                accF[mf][nf][1] += s1 * accC[mf][nf][1];
                accF[mf][nf][2] += s0 * accC[mf][nf][2];
                accF[mf][nf][3] += s1 * accC[mf][nf][3];
            }
        }
        __syncthreads();
        if (kb + 2 < KD / 64) {
            #pragma unroll
            for (int s = 0; s < 4; s++) {
                int off = aoff[s];
                int sz = (off < 0) ? 0 : 16;
                int o = (off < 0) ? 0 : off + (kb + 2) * 128;
                cpasync16(smb + 4096 + buf * 32768 + aswz[s],         (const char*)g_xh + o, sz);
                cpasync16(smb + 4096 + buf * 32768 + 16384 + aswz[s], (const char*)g_xl + o, sz);
            }
            CP_COMMIT;
            #pragma unroll
            for (int i = 0; i < 4; i++)
                bw[i] = (uint32_t)wp[(size_t)((kb + 2) * 8 + jw4[i]) * (2 * ID) + colw[i]];
            if (tid < 128) sreg = sp[(size_t)(kb + 2) * (2 * ID) + scol];
        }
    }

    // epilogue: silu(gate)*up -> hi/lo bf16
    #pragma unroll
    for (int mf = 0; mf < 2; mf++) {
        int r0 = rbase + wm + mf * 16 + (lane >> 2);
        #pragma unroll
        for (int nf = 0; nf < 4; nf++) {
            int icol = n0 + ngw * 32 + nf * 8 + (lane & 3) * 2;
            float* G = accF[mf][nf];
            float* U = accF[mf][nf + 4];
            float a0 = silu_f(G[0]) * U[0];
            float a1 = silu_f(G[1]) * U[1];
            float a2 = silu_f(G[2]) * U[2];
            float a3 = silu_f(G[3]) * U[3];
            float h0 = __bfloat162float(__float2bfloat16_rn(a0));
            float h1 = __bfloat162float(__float2bfloat16_rn(a1));
            float h2 = __bfloat162float(__float2bfloat16_rn(a2));
            float h3 = __bfloat162float(__float2bfloat16_rn(a3));
            *(uint32_t*)(g_ah + (size_t)r0 * ID + icol)       = pk2(h0, h1);
            *(uint32_t*)(g_al + (size_t)r0 * ID + icol)       = pk2(a0 - h0, a1 - h1);
            *(uint32_t*)(g_ah + (size_t)(r0 + 8) * ID + icol) = pk2(h2, h3);
            *(uint32_t*)(g_al + (size_t)(r0 + 8) * ID + icol) = pk2(a2 - h2, a3 - h3);
        }
    }
}

// ---------------------------------------------------------------------------
// down: block = 128 rows x 64 out cols. grid (MAXT, KD/64). 2 CTAs/SM target.
// ---------------------------------------------------------------------------
__global__ __launch_bounds__(256, 2)
void k_dn(const int* __restrict__ dwp, const float* __restrict__ dws,
          const int* __restrict__ sdwp, const float* __restrict__ sdws)
{
    extern __shared__ __align__(16) char sm[];
    int tile = blockIdx.x;
    if (tile >= g_ntiles) return;
    int e = g_tile_e[tile], rbase = g_tile_b[tile];
    int n0 = blockIdx.y * 64;
    const int* wp; const float* sp;
    if (e < NE) { wp = dwp + (size_t)e * (ID / 8) * KD; sp = dws + (size_t)e * (ID / GSZ) * KD; }
    else        { wp = sdwp; sp = sdws; }

    uint32_t* tbl = (uint32_t*)sm;
    float* ss = (float*)(sm + 1024);
    uint32_t smb = smem_u32(sm);
    const int tid = threadIdx.x;

    {
        __nv_bfloat16 l0 = __float2bfloat16(c_lut[tid & 15]);
        __nv_bfloat16 l1 = __float2bfloat16(c_lut[(tid >> 4) & 15]);
        tbl[tid] = (uint32_t)*(uint16_t*)&l0 | ((uint32_t)*(uint16_t*)&l1 << 16);
    }
    __syncthreads();

    int aoff[4]; uint32_t aswz[4];
    #pragma unroll
    for (int s = 0; s < 4; s++) {
        int idx = s * 256 + tid;
        int row = idx >> 3, q = idx & 7;
        aoff[s] = (rbase + row) * (ID * 2) + q * 16;
        aswz[s] = swz128(row * 128 + q * 16);
    }
    int colw[2], jw2[2]; uint32_t dstB[2];
    #pragma unroll
    for (int i = 0; i < 2; i++) {
        int idx = i * 256 + tid;
        int n = idx >> 3, j = idx & 7;
        colw[i] = n0 + n;
        jw2[i] = j;
        dstB[i] = swz128(n * 128 + j * 16);
    }
    int scol = n0 + (tid & 63);

    int lane = tid & 31, wid = tid >> 5;
    int wm = (wid & 3) * 32, ngw = wid >> 2;
    int rowA0 = (wm + (lane & 15)) * 128;
    int khA = lane >> 4;
    int rowBt[2];
    #pragma unroll
    for (int t = 0; t < 2; t++)
        rowBt[t] = (ngw * 32 + t * 16 + (lane & 7) + ((lane >> 4) << 3)) * 128;
    int khB = (lane >> 3) & 1;

    float accF[2][4][4];
    #pragma unroll
    for (int a = 0; a < 2; a++)
        #pragma unroll
        for (int b = 0; b < 4; b++)
            #pragma unroll
            for (int c = 0; c < 4; c++) accF[a][b][c] = 0.f;
    float accC[2][4][4];
    const float zf4[4] = {0.f, 0.f, 0.f, 0.f};

    // ---- prologue ----
    uint32_t bw[2]; float sreg = 0.f;
    #pragma unroll
    for (int i = 0; i < 2; i++) bw[i] = (uint32_t)wp[(size_t)jw2[i] * KD + colw[i]];
    if (tid < 64) sreg = sp[scol];
    {
        char* Bb = sm + 69632;                 // buf 0
        #pragma unroll
        for (int i = 0; i < 2; i++) {
            uint32_t w = bw[i];
            uint4 v;
            v.x = tbl[w & 255];         v.y = tbl[(w >> 8) & 255];
            v.z = tbl[(w >> 16) & 255]; v.w = tbl[w >> 24];
            *(uint4*)(Bb + dstB[i]) = v;
        }
        if (tid < 64) ss[tid] = sreg;
    }
    #pragma unroll
    for (int i = 0; i < 2; i++) bw[i] = (uint32_t)wp[(size_t)(8 + jw2[i]) * KD + colw[i]];
    if (tid < 64) sreg = sp[(size_t)KD + scol];

    #pragma unroll
    for (int s = 0; s < 4; s++) {
        cpasync16(smb + 4096 + aswz[s],         (const char*)g_ah + aoff[s], 16);
        cpasync16(smb + 4096 + 16384 + aswz[s], (const char*)g_al + aoff[s], 16);
    }
    CP_COMMIT;
    #pragma unroll
    for (int s = 0; s < 4; s++) {
        cpasync16(smb + 4096 + 32768 + aswz[s],         (const char*)g_ah + aoff[s] + 128, 16);
        cpasync16(smb + 4096 + 32768 + 16384 + aswz[s], (const char*)g_al + aoff[s] + 128, 16);
    }
    CP_COMMIT;

    for (int ib = 0; ib < ID / 64; ib++) {
        int buf = ib & 1, nb = buf ^ 1;
        if (ib + 1 < ID / 64) { CP_WAIT1; } else { CP_WAIT0; }
        __syncthreads();
        if (ib + 1 < ID / 64) {
            char* Bb = sm + 69632 + nb * 8192;
            #pragma unroll
            for (int i = 0; i < 2; i++) {
                uint32_t w = bw[i];
                uint4 v;
                v.x = tbl[w & 255];         v.y = tbl[(w >> 8) & 255];
                v.z = tbl[(w >> 16) & 255]; v.w = tbl[w >> 24];
                *(uint4*)(Bb + dstB[i]) = v;
            }
            if (tid < 64) ss[nb * 64 + tid] = sreg;
        }
        uint32_t Ab = smb + 4096 + buf * 32768;
        uint32_t Bba = smb + 69632 + buf * 8192;
        #pragma unroll
        for (int ks = 0; ks < 4; ks++) {
            uint32_t bfr[2][4];
            #pragma unroll
            for (int t = 0; t < 2; t++)
                ldmx4(bfr[t], Bba + swz128(rowBt[t] + (ks * 2 + khB) * 16));
            #pragma unroll
            for (int pass = 0; pass < 2; pass++) {
                #pragma unroll
                for (int mf = 0; mf < 2; mf++) {
                    uint32_t a[4];
                    ldmx4(a, Ab + pass * 16384 + swz128(rowA0 + mf * 2048 + (ks * 2 + khA) * 16));
                    #pragma unroll
                    for (int nf = 0; nf < 4; nf++)
                        mma16816(accC[mf][nf], a,
                                 bfr[nf >> 1][(nf & 1) * 2], bfr[nf >> 1][(nf & 1) * 2 + 1],
                                 (ks == 0 && pass == 0) ? zf4 : accC[mf][nf]);
                }
            }
        }
        const float* ssb = ss + buf * 64;
        #pragma unroll
        for (int nf = 0; nf < 4; nf++) {
            int ci = ngw * 32 + nf * 8 + (lane & 3) * 2;
            float s0 = ssb[ci], s1 = ssb[ci + 1];
            #pragma unroll
            for (int mf = 0; mf < 2; mf++) {
                accF[mf][nf][0] += s0 * accC[mf][nf][0];
                accF[mf][nf][1] += s1 * accC[mf][nf][1];
                accF[mf][nf][2] += s0 * accC[mf][nf][2];
                accF[mf][nf][3] += s1 * accC[mf][nf][3];
            }
        }
        __syncthreads();
        if (ib + 2 < ID / 64) {
            #pragma unroll
            for (int s = 0; s < 4; s++) {
                int o = aoff[s] + (ib + 2) * 128;
                cpasync16(smb + 4096 + buf * 32768 + aswz[s],         (const char*)g_ah + o, 16);
                cpasync16(smb + 4096 + buf * 32768 + 16384 + aswz[s], (const char*)g_al + o, 16);
            }
            CP_COMMIT;
            #pragma unroll
            for (int i = 0; i < 2; i++)
                bw[i] = (uint32_t)wp[(size_t)((ib + 2) * 8 + jw2[i]) * KD + colw[i]];
            if (tid < 64) sreg = sp[(size_t)(ib + 2) * KD + scol];
        }
    }

    #pragma unroll
    for (int mf = 0; mf < 2; mf++) {
        int r0 = rbase + wm + mf * 16 + (lane >> 2);
        float w0 = g_w[r0], w1 = g_w[r0 + 8];
        #pragma unroll
        for (int nf = 0; nf < 4; nf++) {
            int col = n0 + ngw * 32 + nf * 8 + (lane & 3) * 2;
            float2 o0, o1;
            o0.x = accF[mf][nf][0] * w0; o0.y = accF[mf][nf][1] * w0;
            o1.x = accF[mf][nf][2] * w1; o1.y = accF[mf][nf][3] * w1;
            *(float2*)(g_y + (size_t)r0 * KD + col)       = o0;
            *(float2*)(g_y + (size_t)(r0 + 8) * KD + col) = o1;
        }
    }
}

// ---------------------------------------------------------------------------
__global__ __launch_bounds__(256) void k_combine(float* __restrict__ out)
{
    int idx = blockIdx.x * blockDim.x + threadIdx.x;
    int t = idx / (KD / 4);
    int kq = (idx % (KD / 4)) * 4;
    int r0 = g_rowof[t * 3 + 0];
    int r1 = g_rowof[t * 3 + 1];
    int r2 = g_rowof[t * 3 + 2];
    float4 a = *(const float4*)&g_y[(size_t)r0 * KD + kq];
    float4 b = *(const float4*)&g_y[(size_t)r1 * KD + kq];
    float4 c = *(const float4*)&g_y[(size_t)r2 * KD + kq];
    float4 o;
    o.x = a.x + b.x + c.x;
    o.y = a.y + b.y + c.y;
    o.z = a.z + b.z + c.z;
    o.w = a.w + b.w + c.w;
    *(float4*)&out[(size_t)t * KD + kq] = o;
}

// ---------------------------------------------------------------------------
extern "C" void kernel_launch(void* const* d_in, const int* in_sizes, int n_in,
                              void* d_out, int out_size)
{
    const float* x     = (const float*)d_in[0];
    const int*   gup   = (const int*)  d_in[1];
    const float* gus   = (const float*)d_in[2];
    const int*   dwp   = (const int*)  d_in[3];
    const float* dws   = (const float*)d_in[4];
    const int*   sgup  = (const int*)  d_in[5];
    const float* sgus  = (const float*)d_in[6];
    const int*   sdwp  = (const int*)  d_in[7];
    const float* sdws  = (const float*)d_in[8];
    const int*   eids  = (const int*)  d_in[9];
    const float* probs = (const float*)d_in[10];
    float* out = (float*)d_out;

    cudaFuncSetAttribute(k_gu, cudaFuncAttributeMaxDynamicSharedMemorySize, GU_SMEM);
    cudaFuncSetAttribute(k_dn, cudaFuncAttributeMaxDynamicSharedMemorySize, DN_SMEM);

    k_route<<<1, 256>>>(eids, probs);
    k_splitx<<<(TT * KD / 4) / 256, 256>>>(x);
    k_gu<<<dim3(MAXT, ID / 64), 256, GU_SMEM>>>(gup, gus, sgup, sgus);
    k_dn<<<dim3(MAXT, KD / 64), 256, DN_SMEM>>>(dwp, dws, sdwp, sdws);
    k_combine<<<(TT * KD / 4) / 256, 256>>>(out);
}

// round 5
// speedup vs baseline: 1.6267x; 1.6267x over previous
#include <cuda_runtime.h>
#include <cuda_fp16.h>
#include <cstdint>

// ---------------- problem dims ----------------
#define TT 2048
#define KD 2048
#define ID 1024
#define NE 8
#define GSZ 64
#define BM 128
#define MAXT 56
#define ROWS_CAP 7168

#define GU_SMEM 69632
#define DN_SMEM 53248

__device__ __constant__ float c_lut[16] = {
    0.0f, 0.5f, 1.0f, 1.5f, 2.0f, 3.0f, 4.0f, 6.0f,
   -0.0f,-0.5f,-1.0f,-1.5f,-2.0f,-3.0f,-4.0f,-6.0f };

// ---------------- scratch ----------------
__device__ int   g_tok[ROWS_CAP];
__device__ float g_w[ROWS_CAP];
__device__ int   g_tile_e[MAXT];
__device__ int   g_tile_b[MAXT];
__device__ int   g_ntiles;
__device__ int   g_rowof[TT * 3];
__device__ __half g_x16[(size_t)TT * KD];
__device__ __half g_a16[(size_t)ROWS_CAP * ID];
__device__ float  g_y[(size_t)ROWS_CAP * KD];

// ---------------- helpers ----------------
static __device__ __forceinline__ uint32_t swz128(uint32_t o) { return o ^ ((o >> 3) & 0x70); }
static __device__ __forceinline__ uint32_t smem_u32(const void* p) {
    uint32_t a;
    asm("{ .reg .u64 t; cvta.to.shared.u64 t, %1; cvt.u32.u64 %0, t; }" : "=r"(a) : "l"(p));
    return a;
}
static __device__ __forceinline__ void ldmx4(uint32_t* r, uint32_t addr) {
    asm volatile("ldmatrix.sync.aligned.m8n8.x4.shared.b16 {%0,%1,%2,%3}, [%4];"
        : "=r"(r[0]), "=r"(r[1]), "=r"(r[2]), "=r"(r[3]) : "r"(addr));
}
static __device__ __forceinline__ void mma16816(float* d, const uint32_t* a,
                                                uint32_t b0, uint32_t b1, const float* c) {
    asm volatile(
        "mma.sync.aligned.m16n8k16.row.col.f32.f16.f16.f32 "
        "{%0,%1,%2,%3},{%4,%5,%6,%7},{%8,%9},{%10,%11,%12,%13};"
        : "=f"(d[0]), "=f"(d[1]), "=f"(d[2]), "=f"(d[3])
        : "r"(a[0]), "r"(a[1]), "r"(a[2]), "r"(a[3]), "r"(b0), "r"(b1),
          "f"(c[0]), "f"(c[1]), "f"(c[2]), "f"(c[3]));
}
static __device__ __forceinline__ void cpasync16(uint32_t dst, const void* src, int srcsize) {
    asm volatile("cp.async.cg.shared.global [%0], [%1], 16, %2;"
                 :: "r"(dst), "l"(src), "r"(srcsize));
}
#define CP_COMMIT asm volatile("cp.async.commit_group;" ::: "memory")
#define CP_WAIT0  asm volatile("cp.async.wait_group 0;" ::: "memory")

static __device__ __forceinline__ uint32_t pkh2(float a, float b) {
    __half2 t = __floats2half2_rn(a, b);
    return *reinterpret_cast<uint32_t*>(&t);
}
static __device__ __forceinline__ float silu_f(float g) { return g / (1.0f + __expf(-g)); }

// ---------------------------------------------------------------------------
// routing
// ---------------------------------------------------------------------------
__global__ void k_route(const int* __restrict__ eids, const float* __restrict__ probs)
{
    __shared__ int cnt[NE];
    __shared__ int offs[NE];
    __shared__ int baseE;
    int tid = threadIdx.x;
    if (tid < NE) cnt[tid] = 0;
    __syncthreads();
    for (int i = tid; i < TT * 2; i += blockDim.x) atomicAdd(&cnt[eids[i]], 1);
    __syncthreads();
    if (tid == 0) {
        int b = 0, tile = 0;
        for (int e = 0; e < NE; e++) {
            offs[e] = b;
            int nt = (cnt[e] + BM - 1) / BM;
            for (int j = 0; j < nt; j++) { g_tile_e[tile] = e; g_tile_b[tile] = b + j * BM; tile++; }
            b += nt * BM;
        }
        baseE = b;
        for (int j = 0; j < TT / BM; j++) { g_tile_e[tile] = NE; g_tile_b[tile] = b + j * BM; tile++; }
        g_ntiles = tile;
    }
    __syncthreads();
    for (int i = tid; i < ROWS_CAP; i += blockDim.x) { g_tok[i] = -1; g_w[i] = 0.0f; }
    __syncthreads();
    for (int i = tid; i < TT * 2; i += blockDim.x) {
        int e = eids[i];
        int pos = atomicAdd(&offs[e], 1);
        int t = i >> 1;
        g_tok[pos] = t;
        g_w[pos] = probs[i];
        g_rowof[t * 3 + (i & 1)] = pos;
    }
    int bs = baseE;
    for (int t = tid; t < TT; t += blockDim.x) {
        g_tok[bs + t] = t;
        g_w[bs + t] = 1.0f;
        g_rowof[t * 3 + 2] = bs + t;
    }
}

// ---------------------------------------------------------------------------
// convert x -> fp16
// ---------------------------------------------------------------------------
__global__ __launch_bounds__(256) void k_cvtx(const float* __restrict__ x)
{
    int idx = blockIdx.x * blockDim.x + threadIdx.x;   // over TT*KD/4
    float4 v = ((const float4*)x)[idx];
    uint2 o = make_uint2(pkh2(v.x, v.y), pkh2(v.z, v.w));
    ((uint2*)g_x16)[idx] = o;
}

// ---------------------------------------------------------------------------
// gate_up: block = 128 rows x (64 gate + 64 up cols). grid (MAXT, ID/64).
// smem: tbl 0..1KB, ss 1KB.., toks 2KB..; A @4096 (2 x 16KB); B @36864 (2 x 16KB).
// ---------------------------------------------------------------------------
__global__ __launch_bounds__(256, 1)
void k_gu(const int* __restrict__ gup, const float* __restrict__ gus,
          const int* __restrict__ sgup, const float* __restrict__ sgus)
{
    extern __shared__ __align__(16) char sm[];
    int tile = blockIdx.x;
    if (tile >= g_ntiles) return;
    int e = g_tile_e[tile], rbase = g_tile_b[tile];
    int n0 = blockIdx.y * 64;
    const int* wp; const float* sp;
    if (e < NE) { wp = gup + (size_t)e * (KD / 8) * (2 * ID); sp = gus + (size_t)e * (KD / GSZ) * (2 * ID); }
    else        { wp = sgup; sp = sgus; }

    uint32_t* tbl = (uint32_t*)sm;
    float* ss = (float*)(sm + 1024);
    int* toks = (int*)(sm + 2048);
    uint32_t smb = smem_u32(sm);
    const int tid = threadIdx.x;

    {
        __half l0 = __float2half(c_lut[tid & 15]);
        __half l1 = __float2half(c_lut[(tid >> 4) & 15]);
        tbl[tid] = (uint32_t)*(uint16_t*)&l0 | ((uint32_t)*(uint16_t*)&l1 << 16);
    }
    if (tid < 128) toks[tid] = g_tok[rbase + tid];
    __syncthreads();

    // A cp.async geometry: 128 rows x 128B, 1024 chunks, 4 per thread
    int aoff[4]; uint32_t aswz[4];
    #pragma unroll
    for (int s = 0; s < 4; s++) {
        int idx = s * 256 + tid;
        int row = idx >> 3, q = idx & 7;
        int tok = toks[row];
        aoff[s] = (tok >= 0) ? (tok * (KD * 2) + q * 16) : -1;
        aswz[s] = swz128(row * 128 + q * 16);
    }
    // B geometry: 1024 words per chunk, 4 per thread
    int colw[4], jw4[4]; uint32_t dstB[4];
    #pragma unroll
    for (int i = 0; i < 4; i++) {
        int idx = i * 256 + tid;
        int n = idx >> 3, j = idx & 7;
        colw[i] = (n < 64) ? (n0 + n) : (ID + n0 + (n - 64));
        jw4[i] = j;
        dstB[i] = swz128(n * 128 + j * 16);
    }
    int scol = (tid < 64) ? (n0 + tid) : (ID + n0 + (tid - 64));

    int lane = tid & 31, wid = tid >> 5;
    int wm = (wid & 3) * 32, ngw = wid >> 2;
    int rowA0 = (wm + (lane & 15)) * 128;
    int khA = lane >> 4;
    int rowBt[4];
    #pragma unroll
    for (int t = 0; t < 4; t++) {
        int base = (t < 2) ? (ngw * 32 + t * 16) : (64 + ngw * 32 + (t - 2) * 16);
        rowBt[t] = (base + (lane & 7) + ((lane >> 4) << 3)) * 128;
    }
    int khB = (lane >> 3) & 1;

    float accF[2][8][4];
    #pragma unroll
    for (int a = 0; a < 2; a++)
        #pragma unroll
        for (int b = 0; b < 8; b++)
            #pragma unroll
            for (int c = 0; c < 4; c++) accF[a][b][c] = 0.f;
    float accC[2][8][4];
    const float zf4[4] = {0.f, 0.f, 0.f, 0.f};

    // prologue: B words + scale for chunk0; cp.async A(0) -> buf0
    uint32_t bw[4]; float sreg = 0.f;
    #pragma unroll
    for (int i = 0; i < 4; i++) bw[i] = (uint32_t)wp[(size_t)jw4[i] * (2 * ID) + colw[i]];
    if (tid < 128) sreg = sp[scol];
    #pragma unroll
    for (int s = 0; s < 4; s++) {
        int off = aoff[s];
        int sz = (off < 0) ? 0 : 16;
        int o = (off < 0) ? 0 : off;
        cpasync16(smb + 4096 + aswz[s], (const char*)g_x16 + o, sz);
    }
    CP_COMMIT;

    for (int kb = 0; kb < KD / 64; kb++) {
        int buf = kb & 1;
        // dequant-store B (exact fp16 codes, scale applied later)
        char* Bb = sm + 36864 + buf * 16384;
        #pragma unroll
        for (int i = 0; i < 4; i++) {
            uint32_t w = bw[i];
            uint4 v;
            v.x = tbl[w & 255];         v.y = tbl[(w >> 8) & 255];
            v.z = tbl[(w >> 16) & 255]; v.w = tbl[w >> 24];
            *(uint4*)(Bb + dstB[i]) = v;
        }
        if (tid < 128) ss[buf * 128 + tid] = sreg;
        CP_WAIT0;
        __syncthreads();
        if (kb + 1 < KD / 64) {
            int nb = buf ^ 1;
            #pragma unroll
            for (int s = 0; s < 4; s++) {
                int off = aoff[s];
                int sz = (off < 0) ? 0 : 16;
                int o = (off < 0) ? 0 : off + (kb + 1) * 128;
                cpasync16(smb + 4096 + nb * 16384 + aswz[s], (const char*)g_x16 + o, sz);
            }
            CP_COMMIT;
            #pragma unroll
            for (int i = 0; i < 4; i++)
                bw[i] = (uint32_t)wp[(size_t)((kb + 1) * 8 + jw4[i]) * (2 * ID) + colw[i]];
            if (tid < 128) sreg = sp[(size_t)(kb + 1) * (2 * ID) + scol];
        }
        // MMA on current buffer (single fp16 pass)
        uint32_t Ab = smb + 4096 + buf * 16384;
        uint32_t Bba = smb + 36864 + buf * 16384;
        #pragma unroll
        for (int ks = 0; ks < 4; ks++) {
            uint32_t bfr[4][4];
            #pragma unroll
            for (int t = 0; t < 4; t++)
                ldmx4(bfr[t], Bba + swz128(rowBt[t] + (ks * 2 + khB) * 16));
            #pragma unroll
            for (int mf = 0; mf < 2; mf++) {
                uint32_t a[4];
                ldmx4(a, Ab + swz128(rowA0 + mf * 2048 + (ks * 2 + khA) * 16));
                #pragma unroll
                for (int nf = 0; nf < 8; nf++)
                    mma16816(accC[mf][nf], a,
                             bfr[nf >> 1][(nf & 1) * 2], bfr[nf >> 1][(nf & 1) * 2 + 1],
                             (ks == 0) ? zf4 : accC[mf][nf]);
            }
        }
        // chunk-scale accumulate in fp32
        const float* ssb = ss + buf * 128;
        #pragma unroll
        for (int nf = 0; nf < 8; nf++) {
            int ci = ((nf < 4) ? 0 : 64) + ngw * 32 + (nf & 3) * 8 + (lane & 3) * 2;
            float s0 = ssb[ci], s1 = ssb[ci + 1];
            #pragma unroll
            for (int mf = 0; mf < 2; mf++) {
                accF[mf][nf][0] += s0 * accC[mf][nf][0];
                accF[mf][nf][1] += s1 * accC[mf][nf][1];
                accF[mf][nf][2] += s0 * accC[mf][nf][2];
                accF[mf][nf][3] += s1 * accC[mf][nf][3];
            }
        }
    }

    // epilogue: silu(gate)*up -> fp16
    #pragma unroll
    for (int mf = 0; mf < 2; mf++) {
        int r0 = rbase + wm + mf * 16 + (lane >> 2);
        #pragma unroll
        for (int nf = 0; nf < 4; nf++) {
            int icol = n0 + ngw * 32 + nf * 8 + (lane & 3) * 2;
            float* G = accF[mf][nf];
            float* U = accF[mf][nf + 4];
            float a0 = silu_f(G[0]) * U[0];
            float a1 = silu_f(G[1]) * U[1];
            float a2 = silu_f(G[2]) * U[2];
            float a3 = silu_f(G[3]) * U[3];
            *(uint32_t*)(g_a16 + (size_t)r0 * ID + icol)       = pkh2(a0, a1);
            *(uint32_t*)(g_a16 + (size_t)(r0 + 8) * ID + icol) = pkh2(a2, a3);
        }
    }
}

// ---------------------------------------------------------------------------
// down: block = 128 rows x 64 out cols. grid (MAXT, KD/64). 2 CTAs/SM.
// smem: tbl 0..1KB, ss 1KB..; A @4096 (2 x 16KB); B @36864 (2 x 8KB).
// ---------------------------------------------------------------------------
__global__ __launch_bounds__(256, 2)
void k_dn(const int* __restrict__ dwp, const float* __restrict__ dws,
          const int* __restrict__ sdwp, const float* __restrict__ sdws)
{
    extern __shared__ __align__(16) char sm[];
    int tile = blockIdx.x;
    if (tile >= g_ntiles) return;
    int e = g_tile_e[tile], rbase = g_tile_b[tile];
    int n0 = blockIdx.y * 64;
    const int* wp; const float* sp;
    if (e < NE) { wp = dwp + (size_t)e * (ID / 8) * KD; sp = dws + (size_t)e * (ID / GSZ) * KD; }
    else        { wp = sdwp; sp = sdws; }

    uint32_t* tbl = (uint32_t*)sm;
    float* ss = (float*)(sm + 1024);
    uint32_t smb = smem_u32(sm);
    const int tid = threadIdx.x;

    {
        __half l0 = __float2half(c_lut[tid & 15]);
        __half l1 = __float2half(c_lut[(tid >> 4) & 15]);
        tbl[tid] = (uint32_t)*(uint16_t*)&l0 | ((uint32_t)*(uint16_t*)&l1 << 16);
    }
    __syncthreads();

    int aoff[4]; uint32_t aswz[4];
    #pragma unroll
    for (int s = 0; s < 4; s++) {
        int idx = s * 256 + tid;
        int row = idx >> 3, q = idx & 7;
        aoff[s] = (rbase + row) * (ID * 2) + q * 16;
        aswz[s] = swz128(row * 128 + q * 16);
    }
    int colw[2], jw2[2]; uint32_t dstB[2];
    #pragma unroll
    for (int i = 0; i < 2; i++) {
        int idx = i * 256 + tid;
        int n = idx >> 3, j = idx & 7;
        colw[i] = n0 + n;
        jw2[i] = j;
        dstB[i] = swz128(n * 128 + j * 16);
    }
    int scol = n0 + (tid & 63);

    int lane = tid & 31, wid = tid >> 5;
    int wm = (wid & 3) * 32, ngw = wid >> 2;
    int rowA0 = (wm + (lane & 15)) * 128;
    int khA = lane >> 4;
    int rowBt[2];
    #pragma unroll
    for (int t = 0; t < 2; t++)
        rowBt[t] = (ngw * 32 + t * 16 + (lane & 7) + ((lane >> 4) << 3)) * 128;
    int khB = (lane >> 3) & 1;

    float accF[2][4][4];
    #pragma unroll
    for (int a = 0; a < 2; a++)
        #pragma unroll
        for (int b = 0; b < 4; b++)
            #pragma unroll
            for (int c = 0; c < 4; c++) accF[a][b][c] = 0.f;
    float accC[2][4][4];
    const float zf4[4] = {0.f, 0.f, 0.f, 0.f};

    uint32_t bw[2]; float sreg = 0.f;
    #pragma unroll
    for (int i = 0; i < 2; i++) bw[i] = (uint32_t)wp[(size_t)jw2[i] * KD + colw[i]];
    if (tid < 64) sreg = sp[scol];
    #pragma unroll
    for (int s = 0; s < 4; s++)
        cpasync16(smb + 4096 + aswz[s], (const char*)g_a16 + aoff[s], 16);
    CP_COMMIT;

    for (int ib = 0; ib < ID / 64; ib++) {
        int buf = ib & 1;
        char* Bb = sm + 36864 + buf * 8192;
        #pragma unroll
        for (int i = 0; i < 2; i++) {
            uint32_t w = bw[i];
            uint4 v;
            v.x = tbl[w & 255];         v.y = tbl[(w >> 8) & 255];
            v.z = tbl[(w >> 16) & 255]; v.w = tbl[w >> 24];
            *(uint4*)(Bb + dstB[i]) = v;
        }
        if (tid < 64) ss[buf * 64 + tid] = sreg;
        CP_WAIT0;
        __syncthreads();
        if (ib + 1 < ID / 64) {
            int nb = buf ^ 1;
            #pragma unroll
            for (int s = 0; s < 4; s++) {
                int o = aoff[s] + (ib + 1) * 128;
                cpasync16(smb + 4096 + nb * 16384 + aswz[s], (const char*)g_a16 + o, 16);
            }
            CP_COMMIT;
            #pragma unroll
            for (int i = 0; i < 2; i++)
                bw[i] = (uint32_t)wp[(size_t)((ib + 1) * 8 + jw2[i]) * KD + colw[i]];
            if (tid < 64) sreg = sp[(size_t)(ib + 1) * KD + scol];
        }
        uint32_t Ab = smb + 4096 + buf * 16384;
        uint32_t Bba = smb + 36864 + buf * 8192;
        #pragma unroll
        for (int ks = 0; ks < 4; ks++) {
            uint32_t bfr[2][4];
            #pragma unroll
            for (int t = 0; t < 2; t++)
                ldmx4(bfr[t], Bba + swz128(rowBt[t] + (ks * 2 + khB) * 16));
            #pragma unroll
            for (int mf = 0; mf < 2; mf++) {
                uint32_t a[4];
                ldmx4(a, Ab + swz128(rowA0 + mf * 2048 + (ks * 2 + khA) * 16));
                #pragma unroll
                for (int nf = 0; nf < 4; nf++)
                    mma16816(accC[mf][nf], a,
                             bfr[nf >> 1][(nf & 1) * 2], bfr[nf >> 1][(nf & 1) * 2 + 1],
                             (ks == 0) ? zf4 : accC[mf][nf]);
            }
        }
        const float* ssb = ss + buf * 64;
        #pragma unroll
        for (int nf = 0; nf < 4; nf++) {
            int ci = ngw * 32 + nf * 8 + (lane & 3) * 2;
            float s0 = ssb[ci], s1 = ssb[ci + 1];
            #pragma unroll
            for (int mf = 0; mf < 2; mf++) {
                accF[mf][nf][0] += s0 * accC[mf][nf][0];
                accF[mf][nf][1] += s1 * accC[mf][nf][1];
                accF[mf][nf][2] += s0 * accC[mf][nf][2];
                accF[mf][nf][3] += s1 * accC[mf][nf][3];
            }
        }
    }

    #pragma unroll
    for (int mf = 0; mf < 2; mf++) {
        int r0 = rbase + wm + mf * 16 + (lane >> 2);
        float w0 = g_w[r0], w1 = g_w[r0 + 8];
        #pragma unroll
        for (int nf = 0; nf < 4; nf++) {
            int col = n0 + ngw * 32 + nf * 8 + (lane & 3) * 2;
            float2 o0, o1;
            o0.x = accF[mf][nf][0] * w0; o0.y = accF[mf][nf][1] * w0;
            o1.x = accF[mf][nf][2] * w1; o1.y = accF[mf][nf][3] * w1;
            *(float2*)(g_y + (size_t)r0 * KD + col)       = o0;
            *(float2*)(g_y + (size_t)(r0 + 8) * KD + col) = o1;
        }
    }
}

// ---------------------------------------------------------------------------
__global__ __launch_bounds__(256) void k_combine(float* __restrict__ out)
{
    int idx = blockIdx.x * blockDim.x + threadIdx.x;
    int t = idx / (KD / 4);
    int kq = (idx % (KD / 4)) * 4;
    int r0 = g_rowof[t * 3 + 0];
    int r1 = g_rowof[t * 3 + 1];
    int r2 = g_rowof[t * 3 + 2];
    float4 a = *(const float4*)&g_y[(size_t)r0 * KD + kq];
    float4 b = *(const float4*)&g_y[(size_t)r1 * KD + kq];
    float4 c = *(const float4*)&g_y[(size_t)r2 * KD + kq];
    float4 o;
    o.x = a.x + b.x + c.x;
    o.y = a.y + b.y + c.y;
    o.z = a.z + b.z + c.z;
    o.w = a.w + b.w + c.w;
    *(float4*)&out[(size_t)t * KD + kq] = o;
}

// ---------------------------------------------------------------------------
extern "C" void kernel_launch(void* const* d_in, const int* in_sizes, int n_in,
                              void* d_out, int out_size)
{
    const float* x     = (const float*)d_in[0];
    const int*   gup   = (const int*)  d_in[1];
    const float* gus   = (const float*)d_in[2];
    const int*   dwp   = (const int*)  d_in[3];
    const float* dws   = (const float*)d_in[4];
    const int*   sgup  = (const int*)  d_in[5];
    const float* sgus  = (const float*)d_in[6];
    const int*   sdwp  = (const int*)  d_in[7];
    const float* sdws  = (const float*)d_in[8];
    const int*   eids  = (const int*)  d_in[9];
    const float* probs = (const float*)d_in[10];
    float* out = (float*)d_out;

    cudaFuncSetAttribute(k_gu, cudaFuncAttributeMaxDynamicSharedMemorySize, GU_SMEM);
    cudaFuncSetAttribute(k_dn, cudaFuncAttributeMaxDynamicSharedMemorySize, DN_SMEM);

    k_route<<<1, 256>>>(eids, probs);
    k_cvtx<<<(TT * KD / 4) / 256, 256>>>(x);
    k_gu<<<dim3(MAXT, ID / 64), 256, GU_SMEM>>>(gup, gus, sgup, sgus);
    k_dn<<<dim3(MAXT, KD / 64), 256, DN_SMEM>>>(dwp, dws, sdwp, sdws);
    k_combine<<<(TT * KD / 4) / 256, 256>>>(out);
}